// round 4
// baseline (speedup 1.0000x reference)
#include <cuda_runtime.h>
#include <cstdint>

#define IN_CHAN 4096
#define BATCH   16
#define NTOT    (3 * IN_CHAN)          // 12288 stacked W rows (q,k,v)
#define KSPLIT  8
#define KS_LEN  (IN_CHAN / KSPLIT)     // 512 k per block
#define ROWS_PB 32                     // rows per block (8 warps x 4 rows)
#define NNODES  32
#define NCHUNK  16
#define CHLEN   (IN_CHAN / NCHUNK)     // 256
#define LOG2E   1.4426950408889634f
#define PI_F    3.14159265358979323846f

// Scratch (device globals; no allocation allowed anywhere)
__device__ float g_part[KSPLIT * NTOT * BATCH];       // split-K partials
__device__ float g_qkv[3 * BATCH * IN_CHAN];          // q,k,v
__device__ float g_range[BATCH * 2];                  // per-batch (center, halfwidth)
__device__ float g_nodes[BATCH][NCHUNK][2][NNODES];   // per j-chunk partial F,G
__device__ float g_cheb[BATCH][2 * NNODES];           // Chebyshev coeffs: F then G

__device__ __forceinline__ void cp_async16(void* smem_ptr, const void* gptr) {
    uint32_t sa = (uint32_t)__cvta_generic_to_shared(smem_ptr);
    asm volatile("cp.async.cg.shared.global [%0], [%1], 16;\n" :: "r"(sa), "l"(gptr));
}
__device__ __forceinline__ float ex2(float x) {
    float r;
    asm("ex2.approx.ftz.f32 %0, %1;" : "=f"(r) : "f"(x));
    return r;
}
// packed f32x2 FMA: d = a*b + d  (component-wise on two fp32 lanes in a 64-bit reg)
__device__ __forceinline__ void fma2(unsigned long long& d,
                                     unsigned long long a, unsigned long long b) {
    asm("fma.rn.f32x2 %0, %1, %2, %0;" : "+l"(d) : "l"(a), "l"(b));
}
__device__ __forceinline__ float2 unpack2(unsigned long long v) {
    float2 f;
    asm("mov.b64 {%0, %1}, %2;" : "=f"(f.x), "=f"(f.y) : "l"(v));
    return f;
}

// ---------------------------------------------------------------------------
// Kernel 1: QKV GEMM, split-K. W streamed straight from HBM (one coalesced
// LDG.128 per lane per 32-k step, prefetch depth 2); x slice in smem read via
// conflict-free broadcast LDS.128. Math in packed f32x2 (FFMA2): 32 packed
// FMA per warp-iter instead of 64 scalar -> FMA floor ~24us, HBM-bound.
// Warp = 4 rows x 8 k-quads. Block 256 thr, 32 rows, 512 k.
// ---------------------------------------------------------------------------
__global__ __launch_bounds__(256) void qkv_gemm_kernel(
    const float* __restrict__ x,
    const float* __restrict__ wq,
    const float* __restrict__ wk,
    const float* __restrict__ wv)
{
    __shared__ float4 xs4[BATCH * (KS_LEN / 4)];   // [b][kk4] 16*128 f4 = 32KB

    const int tid  = threadIdx.x;
    const int wid  = tid >> 5;
    const int lane = tid & 31;
    const int kq   = lane & 7;          // k-quad offset within 8-group
    const int rsub = lane >> 3;         // row within warp (0..3)

    const int gn0 = blockIdx.x * ROWS_PB;
    const int mat = gn0 >> 12;
    const int n0  = gn0 & (IN_CHAN - 1);
    const int kb  = blockIdx.y * KS_LEN;
    const float* w = (mat == 0) ? wq : (mat == 1) ? wk : wv;

    // stage x slice (16 batches x 512 k) via cp.async
#pragma unroll
    for (int i = 0; i < 8; ++i) {
        int idx = tid + i * 256;        // [0,2048)
        int b   = idx >> 7;
        int kk4 = idx & 127;
        cp_async16(&xs4[idx], x + (size_t)b * IN_CHAN + kb + kk4 * 4);
    }
    asm volatile("cp.async.commit_group;\ncp.async.wait_group 0;\n");
    __syncthreads();

    const int row = n0 + wid * 4 + rsub;
    // W stream as 16B packed-pair units; lane strides 8 units (=32 floats)/iter
    const ulonglong2* wp =
        (const ulonglong2*)(w + (size_t)row * IN_CHAN + kb) + kq;
    const ulonglong2* xs2 = (const ulonglong2*)xs4;

    unsigned long long acc2[BATCH];
#pragma unroll
    for (int b = 0; b < BATCH; ++b) acc2[b] = 0ull;   // (0.f,0.f)

    // prefetch depth 2
    ulonglong2 pfA = wp[0];
    ulonglong2 pfB = wp[8];

    int xi = kq;
#pragma unroll 2
    for (int it = 0; it < KS_LEN / 32; ++it) {        // 16 iters
        unsigned long long w01 = pfA.x;
        unsigned long long w23 = pfA.y;
        pfA = pfB;
        if (it < KS_LEN / 32 - 2)
            pfB = wp[(it + 2) * 8];
#pragma unroll
        for (int b = 0; b < BATCH; ++b) {
            ulonglong2 xv = xs2[b * 128 + xi];        // broadcast-4 LDS.128
            fma2(acc2[b], w01, xv.x);
            fma2(acc2[b], w23, xv.y);
        }
        xi += 8;
    }

    // horizontal add of the f32x2 lanes, then reduce across the 8 kq lanes
    float acc[BATCH];
#pragma unroll
    for (int b = 0; b < BATCH; ++b) {
        float2 f = unpack2(acc2[b]);
        acc[b] = f.x + f.y;
        acc[b] += __shfl_xor_sync(0xffffffffu, acc[b], 1);
        acc[b] += __shfl_xor_sync(0xffffffffu, acc[b], 2);
        acc[b] += __shfl_xor_sync(0xffffffffu, acc[b], 4);
    }
    if (kq == 0) {
        const int p  = blockIdx.y;
        const int gn = gn0 + wid * 4 + rsub;
        float* dst = g_part + ((size_t)p * NTOT + gn) * BATCH;
#pragma unroll
        for (int v = 0; v < 4; ++v) {
            float4 o = make_float4(acc[v * 4], acc[v * 4 + 1],
                                   acc[v * 4 + 2], acc[v * 4 + 3]);
            *(float4*)(dst + v * 4) = o;
        }
    }
}

// ---------------------------------------------------------------------------
// Kernel 2: reduce split-K partials + bias -> g_qkv[mat][b][n]
// ---------------------------------------------------------------------------
__global__ __launch_bounds__(256) void reduce_bias_kernel(
    const float* __restrict__ bq,
    const float* __restrict__ bk,
    const float* __restrict__ bv)
{
    int idx = blockIdx.x * 256 + threadIdx.x;
    int n   = idx & (IN_CHAN - 1);
    int b   = (idx >> 12) & (BATCH - 1);
    int mat = idx >> 16;
    int gn  = mat * IN_CHAN + n;

    float s = 0.f;
#pragma unroll
    for (int pp = 0; pp < KSPLIT; ++pp)
        s += g_part[((size_t)pp * NTOT + gn) * BATCH + b];

    const float* bias = (mat == 0) ? bq : (mat == 1) ? bk : bv;
    g_qkv[idx] = s + bias[n];
}

// ---------------------------------------------------------------------------
// Kernel 3: per-batch q range -> (center, halfwidth)
// ---------------------------------------------------------------------------
__global__ __launch_bounds__(256) void q_range_kernel()
{
    __shared__ float smn[8], smx[8];
    const int b   = blockIdx.x;
    const int tid = threadIdx.x;
    const float* q = g_qkv + (size_t)b * IN_CHAN;

    float mn = 3.4e38f, mx = -3.4e38f;
    for (int i = tid; i < IN_CHAN; i += 256) {
        float v = q[i];
        mn = fminf(mn, v);
        mx = fmaxf(mx, v);
    }
#pragma unroll
    for (int o = 16; o; o >>= 1) {
        mn = fminf(mn, __shfl_xor_sync(0xffffffffu, mn, o));
        mx = fmaxf(mx, __shfl_xor_sync(0xffffffffu, mx, o));
    }
    if ((tid & 31) == 0) { smn[tid >> 5] = mn; smx[tid >> 5] = mx; }
    __syncthreads();
    if (tid == 0) {
        for (int i = 1; i < 8; ++i) {
            mn = fminf(mn, smn[i]);
            mx = fmaxf(mx, smx[i]);
        }
        g_range[b * 2]     = 0.5f * (mn + mx);
        g_range[b * 2 + 1] = fmaxf(0.5f * (mx - mn), 1e-6f);
    }
}

// ---------------------------------------------------------------------------
// Kernel 4: evaluate F,G at 32 Chebyshev nodes, partial over a 256-j chunk.
// grid (16 batches, 16 chunks) x 512 thr. thread = (node, j-sublane of 16).
// ---------------------------------------------------------------------------
__global__ __launch_bounds__(512) void attn_nodes_kernel()
{
    __shared__ float ks[CHLEN], vs[CHLEN];
    const int b   = blockIdx.x;
    const int ch  = blockIdx.y;
    const int tid = threadIdx.x;

    const float* kp = g_qkv + (size_t)BATCH * IN_CHAN + (size_t)b * IN_CHAN + ch * CHLEN;
    const float* vp = g_qkv + (size_t)2 * BATCH * IN_CHAN + (size_t)b * IN_CHAN + ch * CHLEN;
    if (tid < CHLEN) {
        ks[tid] = kp[tid];
        vs[tid] = vp[tid];
    }
    __syncthreads();

    const float qc = g_range[b * 2];
    const float qh = g_range[b * 2 + 1];
    const int node = tid >> 4;          // 0..31
    const int sub  = tid & 15;

    const float xt = qc + qh * cosf(PI_F * (node + 0.5f) / NNODES);
    const float a  = xt * LOG2E;

    float aF = 0.f, aG = 0.f;
#pragma unroll
    for (int j = sub; j < CHLEN; j += 16) {
        float e = ex2(a * ks[j]);
        aG += e;
        aF = fmaf(e, vs[j], aF);
    }
#pragma unroll
    for (int o = 8; o; o >>= 1) {
        aF += __shfl_xor_sync(0xffffffffu, aF, o);
        aG += __shfl_xor_sync(0xffffffffu, aG, o);
    }
    if (sub == 0) {
        g_nodes[b][ch][0][node] = aF;
        g_nodes[b][ch][1][node] = aG;
    }
}

// ---------------------------------------------------------------------------
// Kernel 5: reduce chunk partials + DCT -> Chebyshev coefficients.
// grid 16 x 64 thr.  thread m computes c_m for F (tid<32) or G (tid>=32).
// ---------------------------------------------------------------------------
__global__ __launch_bounds__(64) void attn_fit_kernel()
{
    __shared__ float Fv[NNODES], Gv[NNODES], tab[128];
    const int b   = blockIdx.x;
    const int tid = threadIdx.x;

    if (tid < NNODES) {
        float f = 0.f, g = 0.f;
#pragma unroll
        for (int c = 0; c < NCHUNK; ++c) {
            f += g_nodes[b][c][0][tid];
            g += g_nodes[b][c][1][tid];
        }
        Fv[tid] = f;
        Gv[tid] = g;
    }
    for (int u = tid; u < 128; u += 64)
        tab[u] = cosf((PI_F / 64.0f) * (float)u);
    __syncthreads();

    const int m = tid & 31;
    const float* src = (tid < 32) ? Fv : Gv;
    float c = 0.f;
#pragma unroll
    for (int t = 0; t < NNODES; ++t)
        c = fmaf(src[t], tab[(m * (2 * t + 1)) & 127], c);
    g_cheb[b][tid] = c * (2.0f / NNODES);
}

// ---------------------------------------------------------------------------
// Kernel 6: evaluate out[b,i] = F(q_i)/G(q_i) via Clenshaw.
// grid (16, 16) x 256 thr.
// ---------------------------------------------------------------------------
__global__ __launch_bounds__(256) void attn_eval_kernel(float* __restrict__ out)
{
    __shared__ float cF[NNODES], cG[NNODES];
    const int b   = blockIdx.y;
    const int tid = threadIdx.x;

    if (tid < 32)      cF[tid] = g_cheb[b][tid];
    else if (tid < 64) cG[tid - 32] = g_cheb[b][tid];
    __syncthreads();

    const float qc = g_range[b * 2];
    const float qh = g_range[b * 2 + 1];
    const int i = blockIdx.x * 256 + tid;

    float q = g_qkv[(size_t)b * IN_CHAN + i];
    float y = (q - qc) / qh;
    y = fminf(1.f, fmaxf(-1.f, y));
    const float y2 = 2.f * y;

    float f1 = 0.f, f2 = 0.f, g1 = 0.f, g2 = 0.f;
#pragma unroll
    for (int m = NNODES - 1; m >= 1; --m) {
        float tf = fmaf(y2, f1, cF[m] - f2);
        f2 = f1; f1 = tf;
        float tg = fmaf(y2, g1, cG[m] - g2);
        g2 = g1; g1 = tg;
    }
    float F = fmaf(y, f1, 0.5f * cF[0]) - f2;
    float G = fmaf(y, g1, 0.5f * cG[0]) - g2;

    out[(size_t)b * IN_CHAN + i] = F / G;
}

// ---------------------------------------------------------------------------
extern "C" void kernel_launch(void* const* d_in, const int* in_sizes, int n_in,
                              void* d_out, int out_size)
{
    (void)in_sizes; (void)n_in; (void)out_size;
    const float* x  = (const float*)d_in[0];
    const float* wq = (const float*)d_in[1];
    const float* bq = (const float*)d_in[2];
    const float* wk = (const float*)d_in[3];
    const float* bk = (const float*)d_in[4];
    const float* wv = (const float*)d_in[5];
    const float* bv = (const float*)d_in[6];
    float* out = (float*)d_out;

    qkv_gemm_kernel<<<dim3(NTOT / ROWS_PB, KSPLIT), 256>>>(x, wq, wk, wv);
    reduce_bias_kernel<<<(3 * BATCH * IN_CHAN) / 256, 256>>>(bq, bk, bv);
    q_range_kernel<<<BATCH, 256>>>();
    attn_nodes_kernel<<<dim3(BATCH, NCHUNK), 512>>>();
    attn_fit_kernel<<<BATCH, 64>>>();
    attn_eval_kernel<<<dim3(IN_CHAN / 256, BATCH), 256>>>(out);
}

// round 5
// speedup vs baseline: 1.8867x; 1.8867x over previous
#include <cuda_runtime.h>
#include <cstdint>

#define IN_CHAN 4096
#define BATCH   16
#define NTOT    (3 * IN_CHAN)          // 12288 stacked W rows (q,k,v)
#define KSPLIT  8
#define KS_LEN  (IN_CHAN / KSPLIT)     // 512 k per block
#define ROWS_PB 256                    // W rows per block
#define KC      32                     // k per W stage
#define NSTAGES (KS_LEN / KC)          // 16
#define NNODES  32
#define NCHUNK  16
#define CHLEN   (IN_CHAN / NCHUNK)     // 256
#define LOG2E   1.4426950408889634f
#define PI_F    3.14159265358979323846f

#define GEMM_SMEM_BYTES ((2048 + 2 * 2048) * 16)   // x 32KB + W 2x32KB = 96KB

// Scratch (device globals; no allocation allowed anywhere)
__device__ float g_part[KSPLIT * NTOT * BATCH];       // split-K partials
__device__ float g_qkv[3 * BATCH * IN_CHAN];          // q,k,v
__device__ float g_range[BATCH * 2];                  // per-batch (center, halfwidth)
__device__ float g_nodes[BATCH][NCHUNK][2][NNODES];   // per j-chunk partial F,G
__device__ float g_cheb[BATCH][2 * NNODES];           // Chebyshev coeffs: F then G

__device__ __forceinline__ void cp_async16(void* smem_ptr, const void* gptr) {
    uint32_t sa = (uint32_t)__cvta_generic_to_shared(smem_ptr);
    asm volatile("cp.async.cg.shared.global [%0], [%1], 16;\n" :: "r"(sa), "l"(gptr));
}
__device__ __forceinline__ float ex2(float x) {
    float r;
    asm("ex2.approx.ftz.f32 %0, %1;" : "=f"(r) : "f"(x));
    return r;
}

// ---------------------------------------------------------------------------
// Kernel 1: QKV GEMM, split-K.  Block 256 thr = 8 warps; warp (bg=wid>>2,
// rg=wid&3) covers batches bg*8..+8 and rows rg*64..+64; lane owns rows
// {rg*64+l, rg*64+l+32} x 8 batches = 16 accumulators.
// Per k-quad per warp: 2 W LDS.128 (conflict-free via kq^(row&7) swizzle,
// rows consecutive across lanes) + 8 broadcast x LDS.128 vs 64 FFMA
// -> crossbar balanced with FMA pipe; DRAM becomes the binder.
// W double-buffered KC=32 stages via cp.async; x slice staged once.
// ---------------------------------------------------------------------------
__global__ __launch_bounds__(256) void qkv_gemm_kernel(
    const float* __restrict__ x,
    const float* __restrict__ wq,
    const float* __restrict__ wk,
    const float* __restrict__ wv)
{
    extern __shared__ float4 smem[];
    float4* xs4 = smem;                 // [16 b][128 kk4]   (32KB)
    float4* ws4 = smem + 2048;          // [2][256 rows * 8] (64KB)

    const int tid  = threadIdx.x;
    const int wid  = tid >> 5;
    const int lane = tid & 31;
    const int bg   = wid >> 2;          // batch group (0/1): batches bg*8..+8
    const int rg   = wid & 3;           // row group: rows rg*64..+64

    const int gn0 = blockIdx.x * ROWS_PB;
    const int mat = gn0 >> 12;
    const int n0  = gn0 & (IN_CHAN - 1);
    const int kb  = blockIdx.y * KS_LEN;
    const float* w = (mat == 0) ? wq : (mat == 1) ? wk : wv;

    // loader mapping: thread covers rows lr+32i (i=0..7), k-quad lq
    const int lr = tid >> 3;            // 0..31
    const int lq = tid & 7;

    // ---- prologue: x slice + W stage 0 (group A), W stage 1 (group B) ----
#pragma unroll
    for (int i = 0; i < 8; ++i) {
        int idx = tid + i * 256;        // [0,2048)
        int b   = idx >> 7;
        int kk4 = idx & 127;
        cp_async16(&xs4[idx], x + (size_t)b * IN_CHAN + kb + kk4 * 4);
    }
#pragma unroll
    for (int i = 0; i < 8; ++i) {
        int r = lr + i * 32;
        cp_async16(&ws4[r * 8 + (lq ^ (r & 7))],
                   w + (size_t)(n0 + r) * IN_CHAN + kb + lq * 4);
    }
    asm volatile("cp.async.commit_group;\n");
#pragma unroll
    for (int i = 0; i < 8; ++i) {
        int r = lr + i * 32;
        cp_async16(&ws4[2048 + r * 8 + (lq ^ (r & 7))],
                   w + (size_t)(n0 + r) * IN_CHAN + kb + KC + lq * 4);
    }
    asm volatile("cp.async.commit_group;\n");

    float acc[2][8];
#pragma unroll
    for (int r = 0; r < 2; ++r)
#pragma unroll
        for (int b = 0; b < 8; ++b) acc[r][b] = 0.f;

    const int r0 = rg * 64 + lane;      // first owned row
    const int xbase = bg * 8 * 128;     // batch-group offset into xs4

    for (int s = 0; s < NSTAGES; ++s) {
        if (s + 1 < NSTAGES) asm volatile("cp.async.wait_group 1;\n");
        else                 asm volatile("cp.async.wait_group 0;\n");
        __syncthreads();

        const float4* wb = ws4 + (s & 1) * 2048;
        const int kk4s = s * 8;
#pragma unroll
        for (int kq = 0; kq < 8; ++kq) {
            float4 w0 = wb[r0 * 8 + (kq ^ (r0 & 7))];
            float4 w1 = wb[(r0 + 32) * 8 + (kq ^ ((r0 + 32) & 7))];
#pragma unroll
            for (int b = 0; b < 8; ++b) {
                float4 xv = xs4[xbase + b * 128 + kk4s + kq];  // broadcast
                acc[0][b] = fmaf(w0.x, xv.x, acc[0][b]);
                acc[0][b] = fmaf(w0.y, xv.y, acc[0][b]);
                acc[0][b] = fmaf(w0.z, xv.z, acc[0][b]);
                acc[0][b] = fmaf(w0.w, xv.w, acc[0][b]);
                acc[1][b] = fmaf(w1.x, xv.x, acc[1][b]);
                acc[1][b] = fmaf(w1.y, xv.y, acc[1][b]);
                acc[1][b] = fmaf(w1.z, xv.z, acc[1][b]);
                acc[1][b] = fmaf(w1.w, xv.w, acc[1][b]);
            }
        }
        __syncthreads();

        if (s + 2 < NSTAGES) {
            const int k0 = kb + (s + 2) * KC;
            float4* wdst = ws4 + (s & 1) * 2048;
#pragma unroll
            for (int i = 0; i < 8; ++i) {
                int r = lr + i * 32;
                cp_async16(&wdst[r * 8 + (lq ^ (r & 7))],
                           w + (size_t)(n0 + r) * IN_CHAN + k0 + lq * 4);
            }
            asm volatile("cp.async.commit_group;\n");
        }
    }

    // each thread owns complete partials: write 2 rows x 8 batches
    const int p = blockIdx.y;
#pragma unroll
    for (int r = 0; r < 2; ++r) {
        int gn = gn0 + r0 + r * 32;
        float* dst = g_part + ((size_t)p * NTOT + gn) * BATCH + bg * 8;
        *(float4*)dst       = make_float4(acc[r][0], acc[r][1], acc[r][2], acc[r][3]);
        *(float4*)(dst + 4) = make_float4(acc[r][4], acc[r][5], acc[r][6], acc[r][7]);
    }
}

// ---------------------------------------------------------------------------
// Kernel 2: reduce split-K partials + bias -> g_qkv[mat][b][n]
// ---------------------------------------------------------------------------
__global__ __launch_bounds__(256) void reduce_bias_kernel(
    const float* __restrict__ bq,
    const float* __restrict__ bk,
    const float* __restrict__ bv)
{
    int idx = blockIdx.x * 256 + threadIdx.x;
    int n   = idx & (IN_CHAN - 1);
    int b   = (idx >> 12) & (BATCH - 1);
    int mat = idx >> 16;
    int gn  = mat * IN_CHAN + n;

    float s = 0.f;
#pragma unroll
    for (int pp = 0; pp < KSPLIT; ++pp)
        s += g_part[((size_t)pp * NTOT + gn) * BATCH + b];

    const float* bias = (mat == 0) ? bq : (mat == 1) ? bk : bv;
    g_qkv[idx] = s + bias[n];
}

// ---------------------------------------------------------------------------
// Kernel 3: per-batch q range -> (center, halfwidth)
// ---------------------------------------------------------------------------
__global__ __launch_bounds__(256) void q_range_kernel()
{
    __shared__ float smn[8], smx[8];
    const int b   = blockIdx.x;
    const int tid = threadIdx.x;
    const float* q = g_qkv + (size_t)b * IN_CHAN;

    float mn = 3.4e38f, mx = -3.4e38f;
    for (int i = tid; i < IN_CHAN; i += 256) {
        float v = q[i];
        mn = fminf(mn, v);
        mx = fmaxf(mx, v);
    }
#pragma unroll
    for (int o = 16; o; o >>= 1) {
        mn = fminf(mn, __shfl_xor_sync(0xffffffffu, mn, o));
        mx = fmaxf(mx, __shfl_xor_sync(0xffffffffu, mx, o));
    }
    if ((tid & 31) == 0) { smn[tid >> 5] = mn; smx[tid >> 5] = mx; }
    __syncthreads();
    if (tid == 0) {
        for (int i = 1; i < 8; ++i) {
            mn = fminf(mn, smn[i]);
            mx = fmaxf(mx, smx[i]);
        }
        g_range[b * 2]     = 0.5f * (mn + mx);
        g_range[b * 2 + 1] = fmaxf(0.5f * (mx - mn), 1e-6f);
    }
}

// ---------------------------------------------------------------------------
// Kernel 4: evaluate F,G at 32 Chebyshev nodes, partial over a 256-j chunk.
// grid (16 batches, 16 chunks) x 512 thr. thread = (node, j-sublane of 16).
// ---------------------------------------------------------------------------
__global__ __launch_bounds__(512) void attn_nodes_kernel()
{
    __shared__ float ks[CHLEN], vs[CHLEN];
    const int b   = blockIdx.x;
    const int ch  = blockIdx.y;
    const int tid = threadIdx.x;

    const float* kp = g_qkv + (size_t)BATCH * IN_CHAN + (size_t)b * IN_CHAN + ch * CHLEN;
    const float* vp = g_qkv + (size_t)2 * BATCH * IN_CHAN + (size_t)b * IN_CHAN + ch * CHLEN;
    if (tid < CHLEN) {
        ks[tid] = kp[tid];
        vs[tid] = vp[tid];
    }
    __syncthreads();

    const float qc = g_range[b * 2];
    const float qh = g_range[b * 2 + 1];
    const int node = tid >> 4;          // 0..31
    const int sub  = tid & 15;

    const float xt = qc + qh * cosf(PI_F * (node + 0.5f) / NNODES);
    const float a  = xt * LOG2E;

    float aF = 0.f, aG = 0.f;
#pragma unroll
    for (int j = sub; j < CHLEN; j += 16) {
        float e = ex2(a * ks[j]);
        aG += e;
        aF = fmaf(e, vs[j], aF);
    }
#pragma unroll
    for (int o = 8; o; o >>= 1) {
        aF += __shfl_xor_sync(0xffffffffu, aF, o);
        aG += __shfl_xor_sync(0xffffffffu, aG, o);
    }
    if (sub == 0) {
        g_nodes[b][ch][0][node] = aF;
        g_nodes[b][ch][1][node] = aG;
    }
}

// ---------------------------------------------------------------------------
// Kernel 5: reduce chunk partials + DCT -> Chebyshev coefficients.
// grid 16 x 64 thr.  thread m computes c_m for F (tid<32) or G (tid>=32).
// ---------------------------------------------------------------------------
__global__ __launch_bounds__(64) void attn_fit_kernel()
{
    __shared__ float Fv[NNODES], Gv[NNODES], tab[128];
    const int b   = blockIdx.x;
    const int tid = threadIdx.x;

    if (tid < NNODES) {
        float f = 0.f, g = 0.f;
#pragma unroll
        for (int c = 0; c < NCHUNK; ++c) {
            f += g_nodes[b][c][0][tid];
            g += g_nodes[b][c][1][tid];
        }
        Fv[tid] = f;
        Gv[tid] = g;
    }
    for (int u = tid; u < 128; u += 64)
        tab[u] = cosf((PI_F / 64.0f) * (float)u);
    __syncthreads();

    const int m = tid & 31;
    const float* src = (tid < 32) ? Fv : Gv;
    float c = 0.f;
#pragma unroll
    for (int t = 0; t < NNODES; ++t)
        c = fmaf(src[t], tab[(m * (2 * t + 1)) & 127], c);
    g_cheb[b][tid] = c * (2.0f / NNODES);
}

// ---------------------------------------------------------------------------
// Kernel 6: evaluate out[b,i] = F(q_i)/G(q_i) via Clenshaw.
// grid (16, 16) x 256 thr.
// ---------------------------------------------------------------------------
__global__ __launch_bounds__(256) void attn_eval_kernel(float* __restrict__ out)
{
    __shared__ float cF[NNODES], cG[NNODES];
    const int b   = blockIdx.y;
    const int tid = threadIdx.x;

    if (tid < 32)      cF[tid] = g_cheb[b][tid];
    else if (tid < 64) cG[tid - 32] = g_cheb[b][tid];
    __syncthreads();

    const float qc = g_range[b * 2];
    const float qh = g_range[b * 2 + 1];
    const int i = blockIdx.x * 256 + tid;

    float q = g_qkv[(size_t)b * IN_CHAN + i];
    float y = (q - qc) / qh;
    y = fminf(1.f, fmaxf(-1.f, y));
    const float y2 = 2.f * y;

    float f1 = 0.f, f2 = 0.f, g1 = 0.f, g2 = 0.f;
#pragma unroll
    for (int m = NNODES - 1; m >= 1; --m) {
        float tf = fmaf(y2, f1, cF[m] - f2);
        f2 = f1; f1 = tf;
        float tg = fmaf(y2, g1, cG[m] - g2);
        g2 = g1; g1 = tg;
    }
    float F = fmaf(y, f1, 0.5f * cF[0]) - f2;
    float G = fmaf(y, g1, 0.5f * cG[0]) - g2;

    out[(size_t)b * IN_CHAN + i] = F / G;
}

// ---------------------------------------------------------------------------
extern "C" void kernel_launch(void* const* d_in, const int* in_sizes, int n_in,
                              void* d_out, int out_size)
{
    (void)in_sizes; (void)n_in; (void)out_size;
    const float* x  = (const float*)d_in[0];
    const float* wq = (const float*)d_in[1];
    const float* bq = (const float*)d_in[2];
    const float* wk = (const float*)d_in[3];
    const float* bk = (const float*)d_in[4];
    const float* wv = (const float*)d_in[5];
    const float* bv = (const float*)d_in[6];
    float* out = (float*)d_out;

    cudaFuncSetAttribute(qkv_gemm_kernel,
                         cudaFuncAttributeMaxDynamicSharedMemorySize,
                         GEMM_SMEM_BYTES);

    qkv_gemm_kernel<<<dim3(NTOT / ROWS_PB, KSPLIT), 256, GEMM_SMEM_BYTES>>>(
        x, wq, wk, wv);
    reduce_bias_kernel<<<(3 * BATCH * IN_CHAN) / 256, 256>>>(bq, bk, bv);
    q_range_kernel<<<BATCH, 256>>>();
    attn_nodes_kernel<<<dim3(BATCH, NCHUNK), 512>>>();
    attn_fit_kernel<<<BATCH, 64>>>();
    attn_eval_kernel<<<dim3(IN_CHAN / 256, BATCH), 256>>>(out);
}

// round 6
// speedup vs baseline: 1.9313x; 1.0236x over previous
#include <cuda_runtime.h>
#include <cstdint>

#define IN_CHAN 4096
#define BATCH   16
#define NTOT    (3 * IN_CHAN)          // 12288 stacked W rows (q,k,v)
#define KSPLIT  8
#define KS_LEN  (IN_CHAN / KSPLIT)     // 512 k per block
#define ROWS_PB 256                    // W rows per block
#define KC      32                     // k per W stage
#define NSTAGES (KS_LEN / KC)          // 16
#define NNODES  32
#define NCHUNK  16
#define CHLEN   (IN_CHAN / NCHUNK)     // 256
#define LOG2E   1.4426950408889634f
#define PI_F    3.14159265358979323846f

#define GEMM_SMEM_BYTES ((2048 + 2 * 2048) * 16)   // x 32KB + W 2x32KB = 96KB

// Scratch (device globals; no allocation allowed anywhere)
__device__ float g_part[KSPLIT * NTOT * BATCH];       // split-K partials
__device__ float g_qkv[3 * BATCH * IN_CHAN];          // q,k,v
__device__ float g_range[BATCH * 2];                  // per-batch (center, halfwidth)
__device__ float g_nodes[BATCH][NCHUNK][2][NNODES];   // per j-chunk partial F,G
__device__ float g_cheb[BATCH][2 * NNODES];           // Chebyshev coeffs: F then G

__device__ __forceinline__ void cp_async16(void* smem_ptr, const void* gptr) {
    uint32_t sa = (uint32_t)__cvta_generic_to_shared(smem_ptr);
    asm volatile("cp.async.cg.shared.global [%0], [%1], 16;\n" :: "r"(sa), "l"(gptr));
}
__device__ __forceinline__ float ex2(float x) {
    float r;
    asm("ex2.approx.ftz.f32 %0, %1;" : "=f"(r) : "f"(x));
    return r;
}
// packed f32x2 FMA: d = a*b + d (two independent fp32 lanes in one 64-bit reg)
__device__ __forceinline__ void fma2(unsigned long long& d,
                                     unsigned long long a, unsigned long long b) {
    asm("fma.rn.f32x2 %0, %1, %2, %0;" : "+l"(d) : "l"(a), "l"(b));
}
__device__ __forceinline__ unsigned long long pack2(float v) {
    unsigned long long r;
    asm("mov.b64 %0, {%1, %1};" : "=l"(r) : "f"(v));
    return r;
}
__device__ __forceinline__ float2 unpack2(unsigned long long v) {
    float2 f;
    asm("mov.b64 {%0, %1}, %2;" : "=f"(f.x), "=f"(f.y) : "l"(v));
    return f;
}

// ---------------------------------------------------------------------------
// Kernel 1: QKV GEMM, split-K, FFMA2 math.
// Block 256 thr = 8 warps; warp (bg,rg) covers batches bg*8..+8 (= 4 batch
// pairs) and rows rg*64..+64; lane owns rows {rg*64+l, +32} x 4 batch-pairs
// = 8 packed f32x2 accumulators (16 outputs).
// x staged in smem BATCH-PAIR INTERLEAVED: float4 = (b0,b1 @ k),(b0,b1 @ k+1),
// so one broadcast LDS.128 yields two packed operands. W duplicated into both
// lanes via mov.b64 {w,w} (ALU pipe). Per kq per warp: 2 W LDS.128 + 8 x
// LDS.128 (16 wavefronts) + 8 MOV + 32 FFMA2 -> FMA floor halves to ~21us,
// DRAM (~32us) becomes the binder.
// W double-buffered KC=32 stages via cp.async.
// ---------------------------------------------------------------------------
__global__ __launch_bounds__(256) void qkv_gemm_kernel(
    const float* __restrict__ x,
    const float* __restrict__ wq,
    const float* __restrict__ wk,
    const float* __restrict__ wv)
{
    extern __shared__ float4 smem[];
    float4* xs4 = smem;                 // [8 bp][256 kk2] interleaved (32KB)
    float4* ws4 = smem + 2048;          // [2][256 rows * 8] (64KB)

    const int tid  = threadIdx.x;
    const int wid  = tid >> 5;
    const int lane = tid & 31;
    const int bg   = wid >> 2;          // batch group: batch-pairs bg*4..+4
    const int rg   = wid & 3;           // row group: rows rg*64..+64

    const int gn0 = blockIdx.x * ROWS_PB;
    const int mat = gn0 >> 12;
    const int n0  = gn0 & (IN_CHAN - 1);
    const int kb  = blockIdx.y * KS_LEN;
    const float* w = (mat == 0) ? wq : (mat == 1) ? wk : wv;

    // loader mapping for W: thread covers rows lr+32i (i=0..7), k-quad lq
    const int lr = tid >> 3;            // 0..31
    const int lq = tid & 7;

    // ---- prologue: W stage 0 + stage 1 async, then x interleave-staged ----
#pragma unroll
    for (int i = 0; i < 8; ++i) {
        int r = lr + i * 32;
        cp_async16(&ws4[r * 8 + (lq ^ (r & 7))],
                   w + (size_t)(n0 + r) * IN_CHAN + kb + lq * 4);
    }
    asm volatile("cp.async.commit_group;\n");
#pragma unroll
    for (int i = 0; i < 8; ++i) {
        int r = lr + i * 32;
        cp_async16(&ws4[2048 + r * 8 + (lq ^ (r & 7))],
                   w + (size_t)(n0 + r) * IN_CHAN + kb + KC + lq * 4);
    }
    asm volatile("cp.async.commit_group;\n");

    // x slice: interleave batch pairs. xs4[bp*256 + kk2] =
    //   (x[2bp][2kk2], x[2bp+1][2kk2], x[2bp][2kk2+1], x[2bp+1][2kk2+1])
#pragma unroll
    for (int i = 0; i < 8; ++i) {
        int idx = tid + i * 256;        // [0,2048)
        int bp  = idx >> 8;
        int kk2 = idx & 255;
        float2 a = *(const float2*)(x + (size_t)(2 * bp) * IN_CHAN + kb + kk2 * 2);
        float2 c = *(const float2*)(x + (size_t)(2 * bp + 1) * IN_CHAN + kb + kk2 * 2);
        xs4[idx] = make_float4(a.x, c.x, a.y, c.y);
    }

    unsigned long long acc2[2][4];      // [row r0/r0+32][batch pair]
#pragma unroll
    for (int r = 0; r < 2; ++r)
#pragma unroll
        for (int p = 0; p < 4; ++p) acc2[r][p] = 0ull;

    const int r0  = rg * 64 + lane;
    const int bp0 = bg * 4;
    const ulonglong2* xp = (const ulonglong2*)xs4;

    for (int s = 0; s < NSTAGES; ++s) {
        if (s + 1 < NSTAGES) asm volatile("cp.async.wait_group 1;\n");
        else                 asm volatile("cp.async.wait_group 0;\n");
        __syncthreads();    // also makes x STS visible on s==0

        const float4* wb = ws4 + (s & 1) * 2048;
        const int kk2s = s * 16;
#pragma unroll
        for (int kq = 0; kq < 8; ++kq) {
            float4 w0 = wb[r0 * 8 + (kq ^ (r0 & 7))];
            float4 w1 = wb[(r0 + 32) * 8 + (kq ^ ((r0 + 32) & 7))];
            unsigned long long pw0x = pack2(w0.x), pw0y = pack2(w0.y),
                               pw0z = pack2(w0.z), pw0w = pack2(w0.w);
            unsigned long long pw1x = pack2(w1.x), pw1y = pack2(w1.y),
                               pw1z = pack2(w1.z), pw1w = pack2(w1.w);
            const int kk2 = kk2s + kq * 2;
#pragma unroll
            for (int p = 0; p < 4; ++p) {
                ulonglong2 xv01 = xp[(bp0 + p) * 256 + kk2];      // k0,k1 pairs
                ulonglong2 xv23 = xp[(bp0 + p) * 256 + kk2 + 1];  // k2,k3 pairs
                fma2(acc2[0][p], pw0x, xv01.x);
                fma2(acc2[0][p], pw0y, xv01.y);
                fma2(acc2[0][p], pw0z, xv23.x);
                fma2(acc2[0][p], pw0w, xv23.y);
                fma2(acc2[1][p], pw1x, xv01.x);
                fma2(acc2[1][p], pw1y, xv01.y);
                fma2(acc2[1][p], pw1z, xv23.x);
                fma2(acc2[1][p], pw1w, xv23.y);
            }
        }
        __syncthreads();

        if (s + 2 < NSTAGES) {
            const int k0 = kb + (s + 2) * KC;
            float4* wdst = ws4 + (s & 1) * 2048;
#pragma unroll
            for (int i = 0; i < 8; ++i) {
                int r = lr + i * 32;
                cp_async16(&wdst[r * 8 + (lq ^ (r & 7))],
                           w + (size_t)(n0 + r) * IN_CHAN + k0 + lq * 4);
            }
            asm volatile("cp.async.commit_group;\n");
        }
    }

    // each thread owns complete partials: 2 rows x 8 batches
    const int p = blockIdx.y;
#pragma unroll
    for (int r = 0; r < 2; ++r) {
        int gn = gn0 + r0 + r * 32;
        float* dst = g_part + ((size_t)p * NTOT + gn) * BATCH + bg * 8;
        float2 p0 = unpack2(acc2[r][0]);
        float2 p1 = unpack2(acc2[r][1]);
        float2 p2 = unpack2(acc2[r][2]);
        float2 p3 = unpack2(acc2[r][3]);
        *(float4*)dst       = make_float4(p0.x, p0.y, p1.x, p1.y);
        *(float4*)(dst + 4) = make_float4(p2.x, p2.y, p3.x, p3.y);
    }
}

// ---------------------------------------------------------------------------
// Kernel 2: reduce split-K partials + bias -> g_qkv[mat][b][n]
// ---------------------------------------------------------------------------
__global__ __launch_bounds__(256) void reduce_bias_kernel(
    const float* __restrict__ bq,
    const float* __restrict__ bk,
    const float* __restrict__ bv)
{
    int idx = blockIdx.x * 256 + threadIdx.x;
    int n   = idx & (IN_CHAN - 1);
    int b   = (idx >> 12) & (BATCH - 1);
    int mat = idx >> 16;
    int gn  = mat * IN_CHAN + n;

    float s = 0.f;
#pragma unroll
    for (int pp = 0; pp < KSPLIT; ++pp)
        s += g_part[((size_t)pp * NTOT + gn) * BATCH + b];

    const float* bias = (mat == 0) ? bq : (mat == 1) ? bk : bv;
    g_qkv[idx] = s + bias[n];
}

// ---------------------------------------------------------------------------
// Kernel 3: per-batch q range -> (center, halfwidth)
// ---------------------------------------------------------------------------
__global__ __launch_bounds__(256) void q_range_kernel()
{
    __shared__ float smn[8], smx[8];
    const int b   = blockIdx.x;
    const int tid = threadIdx.x;
    const float* q = g_qkv + (size_t)b * IN_CHAN;

    float mn = 3.4e38f, mx = -3.4e38f;
    for (int i = tid; i < IN_CHAN; i += 256) {
        float v = q[i];
        mn = fminf(mn, v);
        mx = fmaxf(mx, v);
    }
#pragma unroll
    for (int o = 16; o; o >>= 1) {
        mn = fminf(mn, __shfl_xor_sync(0xffffffffu, mn, o));
        mx = fmaxf(mx, __shfl_xor_sync(0xffffffffu, mx, o));
    }
    if ((tid & 31) == 0) { smn[tid >> 5] = mn; smx[tid >> 5] = mx; }
    __syncthreads();
    if (tid == 0) {
        for (int i = 1; i < 8; ++i) {
            mn = fminf(mn, smn[i]);
            mx = fmaxf(mx, smx[i]);
        }
        g_range[b * 2]     = 0.5f * (mn + mx);
        g_range[b * 2 + 1] = fmaxf(0.5f * (mx - mn), 1e-6f);
    }
}

// ---------------------------------------------------------------------------
// Kernel 4: evaluate F,G at 32 Chebyshev nodes, partial over a 256-j chunk.
// grid (16 batches, 16 chunks) x 512 thr. thread = (node, j-sublane of 16).
// ---------------------------------------------------------------------------
__global__ __launch_bounds__(512) void attn_nodes_kernel()
{
    __shared__ float ks[CHLEN], vs[CHLEN];
    const int b   = blockIdx.x;
    const int ch  = blockIdx.y;
    const int tid = threadIdx.x;

    const float* kp = g_qkv + (size_t)BATCH * IN_CHAN + (size_t)b * IN_CHAN + ch * CHLEN;
    const float* vp = g_qkv + (size_t)2 * BATCH * IN_CHAN + (size_t)b * IN_CHAN + ch * CHLEN;
    if (tid < CHLEN) {
        ks[tid] = kp[tid];
        vs[tid] = vp[tid];
    }
    __syncthreads();

    const float qc = g_range[b * 2];
    const float qh = g_range[b * 2 + 1];
    const int node = tid >> 4;          // 0..31
    const int sub  = tid & 15;

    const float xt = qc + qh * cosf(PI_F * (node + 0.5f) / NNODES);
    const float a  = xt * LOG2E;

    float aF = 0.f, aG = 0.f;
#pragma unroll
    for (int j = sub; j < CHLEN; j += 16) {
        float e = ex2(a * ks[j]);
        aG += e;
        aF = fmaf(e, vs[j], aF);
    }
#pragma unroll
    for (int o = 8; o; o >>= 1) {
        aF += __shfl_xor_sync(0xffffffffu, aF, o);
        aG += __shfl_xor_sync(0xffffffffu, aG, o);
    }
    if (sub == 0) {
        g_nodes[b][ch][0][node] = aF;
        g_nodes[b][ch][1][node] = aG;
    }
}

// ---------------------------------------------------------------------------
// Kernel 5: reduce chunk partials + DCT -> Chebyshev coefficients.
// grid 16 x 64 thr.  thread m computes c_m for F (tid<32) or G (tid>=32).
// ---------------------------------------------------------------------------
__global__ __launch_bounds__(64) void attn_fit_kernel()
{
    __shared__ float Fv[NNODES], Gv[NNODES], tab[128];
    const int b   = blockIdx.x;
    const int tid = threadIdx.x;

    if (tid < NNODES) {
        float f = 0.f, g = 0.f;
#pragma unroll
        for (int c = 0; c < NCHUNK; ++c) {
            f += g_nodes[b][c][0][tid];
            g += g_nodes[b][c][1][tid];
        }
        Fv[tid] = f;
        Gv[tid] = g;
    }
    for (int u = tid; u < 128; u += 64)
        tab[u] = cosf((PI_F / 64.0f) * (float)u);
    __syncthreads();

    const int m = tid & 31;
    const float* src = (tid < 32) ? Fv : Gv;
    float c = 0.f;
#pragma unroll
    for (int t = 0; t < NNODES; ++t)
        c = fmaf(src[t], tab[(m * (2 * t + 1)) & 127], c);
    g_cheb[b][tid] = c * (2.0f / NNODES);
}

// ---------------------------------------------------------------------------
// Kernel 6: evaluate out[b,i] = F(q_i)/G(q_i) via Clenshaw.
// grid (16, 16) x 256 thr.
// ---------------------------------------------------------------------------
__global__ __launch_bounds__(256) void attn_eval_kernel(float* __restrict__ out)
{
    __shared__ float cF[NNODES], cG[NNODES];
    const int b   = blockIdx.y;
    const int tid = threadIdx.x;

    if (tid < 32)      cF[tid] = g_cheb[b][tid];
    else if (tid < 64) cG[tid - 32] = g_cheb[b][tid];
    __syncthreads();

    const float qc = g_range[b * 2];
    const float qh = g_range[b * 2 + 1];
    const int i = blockIdx.x * 256 + tid;

    float q = g_qkv[(size_t)b * IN_CHAN + i];
    float y = (q - qc) / qh;
    y = fminf(1.f, fmaxf(-1.f, y));
    const float y2 = 2.f * y;

    float f1 = 0.f, f2 = 0.f, g1 = 0.f, g2 = 0.f;
#pragma unroll
    for (int m = NNODES - 1; m >= 1; --m) {
        float tf = fmaf(y2, f1, cF[m] - f2);
        f2 = f1; f1 = tf;
        float tg = fmaf(y2, g1, cG[m] - g2);
        g2 = g1; g1 = tg;
    }
    float F = fmaf(y, f1, 0.5f * cF[0]) - f2;
    float G = fmaf(y, g1, 0.5f * cG[0]) - g2;

    out[(size_t)b * IN_CHAN + i] = F / G;
}

// ---------------------------------------------------------------------------
extern "C" void kernel_launch(void* const* d_in, const int* in_sizes, int n_in,
                              void* d_out, int out_size)
{
    (void)in_sizes; (void)n_in; (void)out_size;
    const float* x  = (const float*)d_in[0];
    const float* wq = (const float*)d_in[1];
    const float* bq = (const float*)d_in[2];
    const float* wk = (const float*)d_in[3];
    const float* bk = (const float*)d_in[4];
    const float* wv = (const float*)d_in[5];
    const float* bv = (const float*)d_in[6];
    float* out = (float*)d_out;

    cudaFuncSetAttribute(qkv_gemm_kernel,
                         cudaFuncAttributeMaxDynamicSharedMemorySize,
                         GEMM_SMEM_BYTES);

    qkv_gemm_kernel<<<dim3(NTOT / ROWS_PB, KSPLIT), 256, GEMM_SMEM_BYTES>>>(
        x, wq, wk, wv);
    reduce_bias_kernel<<<(3 * BATCH * IN_CHAN) / 256, 256>>>(bq, bk, bv);
    q_range_kernel<<<BATCH, 256>>>();
    attn_nodes_kernel<<<dim3(BATCH, NCHUNK), 512>>>();
    attn_fit_kernel<<<BATCH, 64>>>();
    attn_eval_kernel<<<dim3(IN_CHAN / 256, BATCH), 256>>>(out);
}

// round 7
// speedup vs baseline: 2.2402x; 1.1599x over previous
#include <cuda_runtime.h>
#include <cstdint>

#define IN_CHAN 4096
#define BATCH   16
#define NTOT    (3 * IN_CHAN)          // 12288 stacked W rows (q,k,v)
#define KSPLIT  16
#define KS_LEN  (IN_CHAN / KSPLIT)     // 256 k per block
#define ROWS_PB 64                     // W rows per block
#define KC      32                     // k per W stage
#define NSTAGES (KS_LEN / KC)          // 8
#define NNODES  32
#define NCHUNK  16
#define CHLEN   (IN_CHAN / NCHUNK)     // 256
#define LOG2E   1.4426950408889634f
#define PI_F    3.14159265358979323846f

// Scratch (device globals; no allocation allowed anywhere)
__device__ float g_part[KSPLIT * NTOT * BATCH];       // split-K partials (12.6MB, fits L2)
__device__ float g_qkv[3 * BATCH * IN_CHAN];          // q,k,v
__device__ unsigned int g_range_u[BATCH * 2];         // encoded (min,max) per batch
__device__ float g_nodes[BATCH][NCHUNK][2][NNODES];   // per j-chunk partial F,G

__device__ __forceinline__ void cp_async16(void* smem_ptr, const void* gptr) {
    uint32_t sa = (uint32_t)__cvta_generic_to_shared(smem_ptr);
    asm volatile("cp.async.cg.shared.global [%0], [%1], 16;\n" :: "r"(sa), "l"(gptr));
}
__device__ __forceinline__ float ex2(float x) {
    float r;
    asm("ex2.approx.ftz.f32 %0, %1;" : "=f"(r) : "f"(x));
    return r;
}
// packed f32x2 FMA: d = a*b + d
__device__ __forceinline__ void fma2(unsigned long long& d,
                                     unsigned long long a, unsigned long long b) {
    asm("fma.rn.f32x2 %0, %1, %2, %0;" : "+l"(d) : "l"(a), "l"(b));
}
__device__ __forceinline__ unsigned long long pack2(float v) {
    unsigned long long r;
    asm("mov.b64 %0, {%1, %1};" : "=l"(r) : "f"(v));
    return r;
}
__device__ __forceinline__ float2 unpack2(unsigned long long v) {
    float2 f;
    asm("mov.b64 {%0, %1}, %2;" : "=f"(f.x), "=f"(f.y) : "l"(v));
    return f;
}
// monotone float<->uint encoding (order-preserving; atomics stay deterministic)
__device__ __forceinline__ unsigned int enc_f(float f) {
    unsigned int b = __float_as_uint(f);
    return (b & 0x80000000u) ? ~b : (b | 0x80000000u);
}
__device__ __forceinline__ float dec_f(unsigned int u) {
    return (u & 0x80000000u) ? __uint_as_float(u & 0x7FFFFFFFu)
                             : __uint_as_float(~u);
}

// ---------------------------------------------------------------------------
// Kernel 1: QKV GEMM, split-K, FFMA2 math. Small tiles for wave balance:
// 64 rows x 16 batches x 256 k per block, 64 threads, 32KB static smem
// -> 7 CTAs/SM, 3072 blocks / 1036 slots = 2.97 waves (eff 0.99 vs 0.65).
// Warp = 64 rows (lane owns {lane, lane+32}) x 4 batch pairs; per kq:
// 2 W LDS.128 + 8 broadcast x LDS.128 (16 wf) vs 32 FFMA2. x batch-pair
// interleaved so one LDS yields two packed operands. W double-buffered
// KC=32 via cp.async. x reloads hit L2 (x is 256KB total).
// Also initializes g_range_u for the downstream range atomics.
// ---------------------------------------------------------------------------
__global__ __launch_bounds__(64) void qkv_gemm_kernel(
    const float* __restrict__ x,
    const float* __restrict__ wq,
    const float* __restrict__ wk,
    const float* __restrict__ wv)
{
    __shared__ float4 xs4[1024];        // [8 bp][128 kk2] interleaved (16KB)
    __shared__ float4 ws4[2][512];      // [buf][64 rows * 8] (16KB)

    const int tid  = threadIdx.x;
    const int wid  = tid >> 5;          // 0/1 -> batch pairs wid*4..+4
    const int lane = tid & 31;

    const int gn0 = blockIdx.x * ROWS_PB;
    const int mat = gn0 >> 12;
    const int n0  = gn0 & (IN_CHAN - 1);
    const int kb  = blockIdx.y * KS_LEN;
    const float* w = (mat == 0) ? wq : (mat == 1) ? wk : wv;

    // init range keys once (this launch precedes reduce_bias)
    if (blockIdx.x == 0 && blockIdx.y == 0 && tid < BATCH) {
        g_range_u[tid * 2]     = 0xFFFFFFFFu;   // min key
        g_range_u[tid * 2 + 1] = 0u;            // max key
    }

    // W loader: thread covers rows lr+8i (i=0..7), k-quad lq
    const int lr = tid >> 3;            // 0..7
    const int lq = tid & 7;

    // ---- prologue: W stage 0 + stage 1 async ----
#pragma unroll
    for (int i = 0; i < 8; ++i) {
        int r = lr + i * 8;
        cp_async16(&ws4[0][r * 8 + (lq ^ (r & 7))],
                   w + (size_t)(n0 + r) * IN_CHAN + kb + lq * 4);
    }
    asm volatile("cp.async.commit_group;\n");
#pragma unroll
    for (int i = 0; i < 8; ++i) {
        int r = lr + i * 8;
        cp_async16(&ws4[1][r * 8 + (lq ^ (r & 7))],
                   w + (size_t)(n0 + r) * IN_CHAN + kb + KC + lq * 4);
    }
    asm volatile("cp.async.commit_group;\n");

    // x slice, batch-pair interleaved: xs4[bp*128 + kk2] =
    //   (x[2bp][2kk2], x[2bp+1][2kk2], x[2bp][2kk2+1], x[2bp+1][2kk2+1])
#pragma unroll
    for (int i = 0; i < 16; ++i) {
        int idx = tid + i * 64;         // [0,1024)
        int bp  = idx >> 7;
        int kk2 = idx & 127;
        float2 a = *(const float2*)(x + (size_t)(2 * bp) * IN_CHAN + kb + kk2 * 2);
        float2 c = *(const float2*)(x + (size_t)(2 * bp + 1) * IN_CHAN + kb + kk2 * 2);
        xs4[idx] = make_float4(a.x, c.x, a.y, c.y);
    }

    unsigned long long acc2[2][4];      // [row lane/lane+32][batch pair]
#pragma unroll
    for (int r = 0; r < 2; ++r)
#pragma unroll
        for (int p = 0; p < 4; ++p) acc2[r][p] = 0ull;

    const int r0  = lane;
    const int bp0 = wid * 4;
    const ulonglong2* xp = (const ulonglong2*)xs4;

    for (int s = 0; s < NSTAGES; ++s) {
        if (s + 1 < NSTAGES) asm volatile("cp.async.wait_group 1;\n");
        else                 asm volatile("cp.async.wait_group 0;\n");
        __syncthreads();    // also publishes x STS on s==0

        const float4* wb = ws4[s & 1];
        const int kk2s = s * 16;
#pragma unroll
        for (int kq = 0; kq < 8; ++kq) {
            float4 w0 = wb[r0 * 8 + (kq ^ (r0 & 7))];
            float4 w1 = wb[(r0 + 32) * 8 + (kq ^ ((r0 + 32) & 7))];
            unsigned long long pw0x = pack2(w0.x), pw0y = pack2(w0.y),
                               pw0z = pack2(w0.z), pw0w = pack2(w0.w);
            unsigned long long pw1x = pack2(w1.x), pw1y = pack2(w1.y),
                               pw1z = pack2(w1.z), pw1w = pack2(w1.w);
            const int kk2 = kk2s + kq * 2;
#pragma unroll
            for (int p = 0; p < 4; ++p) {
                ulonglong2 xv01 = xp[(bp0 + p) * 128 + kk2];
                ulonglong2 xv23 = xp[(bp0 + p) * 128 + kk2 + 1];
                fma2(acc2[0][p], pw0x, xv01.x);
                fma2(acc2[0][p], pw0y, xv01.y);
                fma2(acc2[0][p], pw0z, xv23.x);
                fma2(acc2[0][p], pw0w, xv23.y);
                fma2(acc2[1][p], pw1x, xv01.x);
                fma2(acc2[1][p], pw1y, xv01.y);
                fma2(acc2[1][p], pw1z, xv23.x);
                fma2(acc2[1][p], pw1w, xv23.y);
            }
        }
        __syncthreads();

        if (s + 2 < NSTAGES) {
            const int k0 = kb + (s + 2) * KC;
            float4* wdst = ws4[s & 1];
#pragma unroll
            for (int i = 0; i < 8; ++i) {
                int r = lr + i * 8;
                cp_async16(&wdst[r * 8 + (lq ^ (r & 7))],
                           w + (size_t)(n0 + r) * IN_CHAN + k0 + lq * 4);
            }
            asm volatile("cp.async.commit_group;\n");
        }
    }

    // store: 2 rows x 8 batches per thread
    const int p = blockIdx.y;
#pragma unroll
    for (int r = 0; r < 2; ++r) {
        int gn = gn0 + r0 + r * 32;
        float* dst = g_part + ((size_t)p * NTOT + gn) * BATCH + wid * 8;
        float2 p0 = unpack2(acc2[r][0]);
        float2 p1 = unpack2(acc2[r][1]);
        float2 p2 = unpack2(acc2[r][2]);
        float2 p3 = unpack2(acc2[r][3]);
        *(float4*)dst       = make_float4(p0.x, p0.y, p1.x, p1.y);
        *(float4*)(dst + 4) = make_float4(p2.x, p2.y, p3.x, p3.y);
    }
}

// ---------------------------------------------------------------------------
// Kernel 2: reduce split-K partials + bias -> g_qkv, and fold the per-batch
// q-range reduction in (deterministic min/max atomics on encoded uints).
// Each block covers 256 consecutive n of one (mat, b).
// ---------------------------------------------------------------------------
__global__ __launch_bounds__(256) void reduce_bias_kernel(
    const float* __restrict__ bq,
    const float* __restrict__ bk,
    const float* __restrict__ bv)
{
    __shared__ float smn[8], smx[8];
    const int tid = threadIdx.x;
    int idx = blockIdx.x * 256 + tid;
    int n   = idx & (IN_CHAN - 1);
    int b   = (idx >> 12) & (BATCH - 1);
    int mat = idx >> 16;
    int gn  = mat * IN_CHAN + n;

    float s = 0.f;
#pragma unroll
    for (int pp = 0; pp < KSPLIT; ++pp)
        s += g_part[((size_t)pp * NTOT + gn) * BATCH + b];

    const float* bias = (mat == 0) ? bq : (mat == 1) ? bk : bv;
    float val = s + bias[n];
    g_qkv[idx] = val;

    if (mat == 0) {                     // uniform per block
        float mn = val, mx = val;
#pragma unroll
        for (int o = 16; o; o >>= 1) {
            mn = fminf(mn, __shfl_xor_sync(0xffffffffu, mn, o));
            mx = fmaxf(mx, __shfl_xor_sync(0xffffffffu, mx, o));
        }
        if ((tid & 31) == 0) { smn[tid >> 5] = mn; smx[tid >> 5] = mx; }
        __syncthreads();
        if (tid == 0) {
            for (int i = 1; i < 8; ++i) {
                mn = fminf(mn, smn[i]);
                mx = fmaxf(mx, smx[i]);
            }
            atomicMin(&g_range_u[b * 2],     enc_f(mn));
            atomicMax(&g_range_u[b * 2 + 1], enc_f(mx));
        }
    }
}

// ---------------------------------------------------------------------------
// Kernel 3: evaluate F,G at 32 Chebyshev nodes, partial over a 256-j chunk.
// grid (16 batches, 16 chunks) x 512 thr. thread = (node, j-sublane of 16).
// ---------------------------------------------------------------------------
__global__ __launch_bounds__(512) void attn_nodes_kernel()
{
    __shared__ float ks[CHLEN], vs[CHLEN];
    const int b   = blockIdx.x;
    const int ch  = blockIdx.y;
    const int tid = threadIdx.x;

    const float* kp = g_qkv + (size_t)BATCH * IN_CHAN + (size_t)b * IN_CHAN + ch * CHLEN;
    const float* vp = g_qkv + (size_t)2 * BATCH * IN_CHAN + (size_t)b * IN_CHAN + ch * CHLEN;
    if (tid < CHLEN) {
        ks[tid] = kp[tid];
        vs[tid] = vp[tid];
    }
    __syncthreads();

    const float mn = dec_f(g_range_u[b * 2]);
    const float mx = dec_f(g_range_u[b * 2 + 1]);
    const float qc = 0.5f * (mn + mx);
    const float qh = fmaxf(0.5f * (mx - mn), 1e-6f);

    const int node = tid >> 4;          // 0..31
    const int sub  = tid & 15;

    const float xt = qc + qh * cosf(PI_F * (node + 0.5f) / NNODES);
    const float a  = xt * LOG2E;

    float aF = 0.f, aG = 0.f;
#pragma unroll
    for (int j = sub; j < CHLEN; j += 16) {
        float e = ex2(a * ks[j]);
        aG += e;
        aF = fmaf(e, vs[j], aF);
    }
#pragma unroll
    for (int o = 8; o; o >>= 1) {
        aF += __shfl_xor_sync(0xffffffffu, aF, o);
        aG += __shfl_xor_sync(0xffffffffu, aG, o);
    }
    if (sub == 0) {
        g_nodes[b][ch][0][node] = aF;
        g_nodes[b][ch][1][node] = aG;
    }
}

// ---------------------------------------------------------------------------
// Kernel 4: fused fit + eval.  Each block: sum node chunks, 32x32 DCT ->
// Chebyshev coeffs (redundant per block, trivial), then Clenshaw per output.
// grid (16 x-chunks, 16 batches) x 256 thr.
// ---------------------------------------------------------------------------
__global__ __launch_bounds__(256) void attn_eval_kernel(float* __restrict__ out)
{
    __shared__ float Fv[NNODES], Gv[NNODES], tab[128], cF[NNODES], cG[NNODES];
    const int b   = blockIdx.y;
    const int tid = threadIdx.x;

    if (tid < 64) {
        int node = tid & 31;
        int sel  = tid >> 5;
        float v = 0.f;
#pragma unroll
        for (int ch = 0; ch < NCHUNK; ++ch)
            v += g_nodes[b][ch][sel][node];
        if (sel == 0) Fv[node] = v;
        else          Gv[node] = v;
    }
    if (tid < 128)
        tab[tid] = cosf((PI_F / 64.0f) * (float)tid);
    __syncthreads();

    if (tid < 64) {
        int m = tid & 31;
        const float* src = (tid < 32) ? Fv : Gv;
        float c = 0.f;
#pragma unroll
        for (int t = 0; t < NNODES; ++t)
            c = fmaf(src[t], tab[(m * (2 * t + 1)) & 127], c);
        c *= 2.0f / NNODES;
        if (tid < 32) cF[m] = c;
        else          cG[m] = c;
    }
    __syncthreads();

    const float mn = dec_f(g_range_u[b * 2]);
    const float mx = dec_f(g_range_u[b * 2 + 1]);
    const float qc = 0.5f * (mn + mx);
    const float qh = fmaxf(0.5f * (mx - mn), 1e-6f);

    const int i = blockIdx.x * 256 + tid;
    float q = g_qkv[(size_t)b * IN_CHAN + i];
    float y = (q - qc) / qh;
    y = fminf(1.f, fmaxf(-1.f, y));
    const float y2 = 2.f * y;

    float f1 = 0.f, f2 = 0.f, g1 = 0.f, g2 = 0.f;
#pragma unroll
    for (int m = NNODES - 1; m >= 1; --m) {
        float tf = fmaf(y2, f1, cF[m] - f2);
        f2 = f1; f1 = tf;
        float tg = fmaf(y2, g1, cG[m] - g2);
        g2 = g1; g1 = tg;
    }
    float F = fmaf(y, f1, 0.5f * cF[0]) - f2;
    float G = fmaf(y, g1, 0.5f * cG[0]) - g2;

    out[(size_t)b * IN_CHAN + i] = F / G;
}

// ---------------------------------------------------------------------------
extern "C" void kernel_launch(void* const* d_in, const int* in_sizes, int n_in,
                              void* d_out, int out_size)
{
    (void)in_sizes; (void)n_in; (void)out_size;
    const float* x  = (const float*)d_in[0];
    const float* wq = (const float*)d_in[1];
    const float* bq = (const float*)d_in[2];
    const float* wk = (const float*)d_in[3];
    const float* bk = (const float*)d_in[4];
    const float* wv = (const float*)d_in[5];
    const float* bv = (const float*)d_in[6];
    float* out = (float*)d_out;

    qkv_gemm_kernel<<<dim3(NTOT / ROWS_PB, KSPLIT), 64>>>(x, wq, wk, wv);
    reduce_bias_kernel<<<(3 * BATCH * IN_CHAN) / 256, 256>>>(bq, bk, bv);
    attn_nodes_kernel<<<dim3(BATCH, NCHUNK), 512>>>();
    attn_eval_kernel<<<dim3(IN_CHAN / 256, BATCH), 256>>>(out);
}